// round 14
// baseline (speedup 1.0000x reference)
#include <cuda_runtime.h>
#include <cstdint>

// ---------------------------------------------------------------------------
// EquivariantMessagePassing — GB300 sm_103a — Round 13
//
//   h_e = silu( A[row] + B[col] + dist_sq * Wx1[128,:] )   (A has bx1 baked in)
//   msg_x_e = h_e @ Wx2 + bx2    -> red.global.add.v4.f32 scatter to out_x[col]
//   pos_upd = wpos[row]*rel_pos  -> atomic scatter to out_pos[col]
// R13: PERSISTENT edge blocks (592 blocks loop over tiles; Wfrag staged once
// per block instead of 7813x) + tanh-based silu (1 MUFU instead of 2).
// Edge GEMM: single-term tf32 MMA, permuted A/B layout, 32 edges/warp.
// ---------------------------------------------------------------------------

#define MAX_N 100000
#define F_DIM 64
#define H_DIM 128
#define EDGE_BLOCKS 592

__device__ float  g_A[(size_t)MAX_N * H_DIM];     // permuted rows
__device__ float  g_B[(size_t)MAX_N * H_DIM];     // permuted rows
__device__ float  g_wpos[MAX_N];
__device__ int    g_idx_is64;
__device__ float2 g_Wfrag[16 * 8 * 32];           // [t][n][lane] = (b0hi, b1hi)
__device__ float  g_w128p[H_DIM];                 // permuted dist_sq weight row

__device__ __forceinline__ float silu_f(float v) {
    float t;
    asm("tanh.approx.f32 %0, %1;" : "=f"(t) : "f"(v * 0.5f));
    return v * fmaf(t, 0.5f, 0.5f);
}

__device__ __forceinline__ unsigned tf32_rnd(float v) {
    unsigned r;
    asm("cvt.rna.tf32.f32 %0, %1;" : "=r"(r) : "f"(v));
    return r;
}

__device__ __forceinline__ void mma_tf32(float acc[4],
                                         unsigned a0, unsigned a1, unsigned a2, unsigned a3,
                                         unsigned b0, unsigned b1) {
    asm volatile(
        "mma.sync.aligned.m16n8k8.row.col.f32.tf32.tf32.f32 "
        "{%0,%1,%2,%3}, {%4,%5,%6,%7}, {%8,%9}, {%0,%1,%2,%3};"
        : "+f"(acc[0]), "+f"(acc[1]), "+f"(acc[2]), "+f"(acc[3])
        : "r"(a0), "r"(a1), "r"(a2), "r"(a3), "r"(b0), "r"(b1));
}

__device__ __forceinline__ void load_edge(const void* ei, int e, int E, int is64,
                                          int nNodes, int& r, int& c)
{
    long long rv, cv;
    if (is64) {
        rv = ((const long long*)ei)[e];
        cv = ((const long long*)ei)[(size_t)E + e];
    } else {
        rv = ((const int*)ei)[e];
        cv = ((const int*)ei)[(size_t)E + e];
    }
    r = (rv >= 0 && rv < nNodes) ? (int)rv : -1;
    c = (cv >= 0 && cv < nNodes) ? (int)cv : -1;
    if (r < 0) c = -1;
}

// permutation: k = c*32 + h*16 + 4j + q  ->  p = j*32 + h*16 + c*4 + q
__device__ __host__ __forceinline__ int permute_k(int k) {
    int c = k >> 5;
    int rem = k & 31;
    int h = rem >> 4;
    int j = (rem >> 2) & 3;
    int q = k & 3;
    return j * 32 + h * 16 + c * 4 + q;
}

// gather + silu for one edge at permuted offsets off0 (h=0) / off1 (h=1)
__device__ __forceinline__ void gather_h(const float* pr, const float* pc,
                                         float dsq, bool ok,
                                         const float4& w40, const float4& w41,
                                         int off0, int off1,
                                         float h0[4], float h1[4])
{
    if (ok) {
        float4 a0 = *(const float4*)(pr + off0);
        float4 b0 = *(const float4*)(pc + off0);
        float4 a1 = *(const float4*)(pr + off1);
        float4 b1 = *(const float4*)(pc + off1);
        h0[0] = silu_f(a0.x + b0.x + dsq * w40.x);
        h0[1] = silu_f(a0.y + b0.y + dsq * w40.y);
        h0[2] = silu_f(a0.z + b0.z + dsq * w40.z);
        h0[3] = silu_f(a0.w + b0.w + dsq * w40.w);
        h1[0] = silu_f(a1.x + b1.x + dsq * w41.x);
        h1[1] = silu_f(a1.y + b1.y + dsq * w41.y);
        h1[2] = silu_f(a1.z + b1.z + dsq * w41.z);
        h1[3] = silu_f(a1.w + b1.w + dsq * w41.w);
    } else {
#pragma unroll
        for (int q = 0; q < 4; q++) { h0[q] = 0.f; h1[q] = 0.f; }
    }
}

// ---------------------------------------------------------------------------
// Kernel 1: per-node precompute (FFMA) + output zeroing + (block 0) prep
// ---------------------------------------------------------------------------
__global__ __launch_bounds__(128) void node_precompute(
    const float* __restrict__ x,
    const float* __restrict__ Wx1, const float* __restrict__ bx1,
    const float* __restrict__ Wx2,
    const float* __restrict__ Wp1, const float* __restrict__ bp1,
    const float* __restrict__ Wp2, const float* __restrict__ bp2,
    const long long* __restrict__ ei, int nCheck,
    float* __restrict__ out0, size_t zeroCount,
    int nNodes)
{
    const int NPB = 8;
    __shared__ float xs[NPB * F_DIM];
    __shared__ float wpart[4][NPB];

    int n0  = blockIdx.x * NPB;
    int tid = threadIdx.x;

    if (blockIdx.x == 0) {
        if (tid == 0) {
            int is64 = 1;
            for (int i = 0; i < nCheck; i++) {
                long long v = ei[i];
                if (v < 0 || v >= (long long)nNodes) { is64 = 0; break; }
            }
            g_idx_is64 = is64;
        }
        if (tid < H_DIM)
            g_w128p[permute_k(tid)] = Wx1[H_DIM * H_DIM + tid];
        for (int i = tid; i < 16 * 8 * 32; i += 128) {
            int lane = i & 31;
            int n    = (i >> 5) & 7;
            int t    = i >> 8;
            int c    = lane & 3;
            int gid  = lane >> 2;
            int col  = n * 8 + gid;
            int k0   = c * 32 + t;
            int k1   = k0 + 16;
            unsigned h0 = tf32_rnd(Wx2[k0 * F_DIM + col]);
            unsigned h1 = tf32_rnd(Wx2[k1 * F_DIM + col]);
            g_Wfrag[i] = make_float2(__uint_as_float(h0), __uint_as_float(h1));
        }
    }

    for (size_t i = (size_t)blockIdx.x * blockDim.x + tid; i < zeroCount;
         i += (size_t)gridDim.x * blockDim.x)
        out0[i] = 0.0f;

    for (int i = tid; i < NPB * F_DIM; i += 128) {
        int node = n0 + (i >> 6);
        xs[i] = (node < nNodes) ? x[(size_t)n0 * F_DIM + i] : 0.0f;
    }
    __syncthreads();

    float accA[NPB], accB[NPB], accP[NPB];
#pragma unroll
    for (int m = 0; m < NPB; m++) { accA[m] = 0.f; accB[m] = 0.f; accP[m] = 0.f; }

    const float* wx1a = Wx1 + tid;
    const float* wx1b = Wx1 + 64 * H_DIM + tid;
    const float* wp1c = Wp1 + tid;

#pragma unroll 4
    for (int k = 0; k < F_DIM; k++) {
        float w1 = wx1a[k * H_DIM];
        float w2 = wx1b[k * H_DIM];
        float wp = wp1c[k * H_DIM];
#pragma unroll
        for (int m = 0; m < NPB; m++) {
            float xv = xs[m * F_DIM + k];
            accA[m] = fmaf(xv, w1, accA[m]);
            accB[m] = fmaf(xv, w2, accB[m]);
            accP[m] = fmaf(xv, wp, accP[m]);
        }
    }

    float b1  = bx1[tid];
    float bp  = bp1[tid];
    float w2v = Wp2[tid];
    int   pt  = permute_k(tid);   // permuted column for A/B stores

#pragma unroll
    for (int m = 0; m < NPB; m++) {
        int node = n0 + m;
        if (node < nNodes) {
            g_A[(size_t)node * H_DIM + pt] = accA[m] + b1;
            g_B[(size_t)node * H_DIM + pt] = accB[m];
        }
        float hv = accP[m] + bp;
        float contrib = silu_f(hv) * w2v;
#pragma unroll
        for (int off = 16; off; off >>= 1)
            contrib += __shfl_xor_sync(0xffffffffu, contrib, off);
        if ((tid & 31) == 0) wpart[tid >> 5][m] = contrib;
    }
    __syncthreads();

    if (tid < NPB) {
        int node = n0 + tid;
        if (node < nNodes)
            g_wpos[node] = wpart[0][tid] + wpart[1][tid] + wpart[2][tid] + wpart[3][tid] + bp2[0];
    }
}

// ---------------------------------------------------------------------------
// Kernel 2: PERSISTENT edge kernel. 592 blocks x 128 threads, 4 blocks/SM.
// Each block stages Wfrag once, then loops over 128-edge tiles.
// 32 edges/warp (two m16 tiles), single-term tf32 MMA.
// ---------------------------------------------------------------------------
__global__ __launch_bounds__(128, 4) void edge_kernel(
    const float* __restrict__ pos,
    const void*  __restrict__ ei,
    const float* __restrict__ bx2,
    float* __restrict__ outx,           // [N, 64]
    float* __restrict__ outpos,         // [N, 3]
    int E, int nNodes)
{
    extern __shared__ float2 sWf[];     // 16*8*32 float2 = 32KB

    const unsigned FULL = 0xffffffffu;
    int tid   = threadIdx.x;
    int lane  = tid & 31;
    int warp  = tid >> 5;
    int is64  = g_idx_is64;

    // ---- one-time Wfrag stage ----
#pragma unroll
    for (int i = 0; i < 32; i++)
        sWf[i * 128 + tid] = g_Wfrag[i * 128 + tid];
    __syncthreads();   // sWf read-only hereafter; no barriers inside the loop

    int gid = lane >> 2;
    int c   = lane & 3;
    bool evenc = ((c & 1) == 0);
    int  colBase0 = evenc ? (2 * c) : (2 * c - 2);

    for (int base = blockIdx.x * 128; base < E; base += EDGE_BLOCKS * 128) {
        int warpE = base + warp * 32;

        // ---- per-lane edge (one edge per lane, 32 edges/warp) ----
        int   rIdx = -1, cIdx = -1;
        float dsq  = 0.f;
        {
            int gE = warpE + lane;
            if (gE < E) load_edge(ei, gE, E, is64, nNodes, rIdx, cIdx);
            if (cIdx >= 0) {
                float dx = pos[rIdx * 3 + 0] - pos[cIdx * 3 + 0];
                float dy = pos[rIdx * 3 + 1] - pos[cIdx * 3 + 1];
                float dz = pos[rIdx * 3 + 2] - pos[cIdx * 3 + 2];
                dsq = dx * dx + dy * dy + dz * dz;
                float wp = g_wpos[rIdx];
                atomicAdd(&outpos[(size_t)cIdx * 3 + 0], wp * dx);
                atomicAdd(&outpos[(size_t)cIdx * 3 + 1], wp * dy);
                atomicAdd(&outpos[(size_t)cIdx * 3 + 2], wp * dz);
            }
        }

        int   rowA0 = __shfl_sync(FULL, rIdx, gid);
        int   colA0 = __shfl_sync(FULL, cIdx, gid);
        float dsqA0 = __shfl_sync(FULL, dsq,  gid);
        int   rowB0 = __shfl_sync(FULL, rIdx, gid + 8);
        int   colB0 = __shfl_sync(FULL, cIdx, gid + 8);
        float dsqB0 = __shfl_sync(FULL, dsq,  gid + 8);
        int   rowA1 = __shfl_sync(FULL, rIdx, gid + 16);
        int   colA1 = __shfl_sync(FULL, cIdx, gid + 16);
        float dsqA1 = __shfl_sync(FULL, dsq,  gid + 16);
        int   rowB1 = __shfl_sync(FULL, rIdx, gid + 24);
        int   colB1 = __shfl_sync(FULL, cIdx, gid + 24);
        float dsqB1 = __shfl_sync(FULL, dsq,  gid + 24);

        bool okA0 = (colA0 >= 0), okB0 = (colB0 >= 0);
        bool okA1 = (colA1 >= 0), okB1 = (colB1 >= 0);
        const float* pAr0 = okA0 ? g_A + (size_t)rowA0 * H_DIM : g_A;
        const float* pAc0 = okA0 ? g_B + (size_t)colA0 * H_DIM : g_B;
        const float* pBr0 = okB0 ? g_A + (size_t)rowB0 * H_DIM : g_A;
        const float* pBc0 = okB0 ? g_B + (size_t)colB0 * H_DIM : g_B;
        const float* pAr1 = okA1 ? g_A + (size_t)rowA1 * H_DIM : g_A;
        const float* pAc1 = okA1 ? g_B + (size_t)colA1 * H_DIM : g_B;
        const float* pBr1 = okB1 ? g_A + (size_t)rowB1 * H_DIM : g_A;
        const float* pBc1 = okB1 ? g_B + (size_t)colB1 * H_DIM : g_B;

        float acc0[8][4], acc1[8][4];
#pragma unroll
        for (int n = 0; n < 8; n++)
#pragma unroll
            for (int q = 0; q < 4; q++) { acc0[n][q] = 0.f; acc1[n][q] = 0.f; }

#pragma unroll
        for (int j = 0; j < 4; j++) {
            int off0 = j * 32 + c * 4;
            int off1 = off0 + 16;
            float4 w40 = *(const float4*)(g_w128p + off0);
            float4 w41 = *(const float4*)(g_w128p + off1);

            float hA0_0[4], hA0_1[4], hB0_0[4], hB0_1[4];
            float hA1_0[4], hA1_1[4], hB1_0[4], hB1_1[4];
            gather_h(pAr0, pAc0, dsqA0, okA0, w40, w41, off0, off1, hA0_0, hA0_1);
            gather_h(pBr0, pBc0, dsqB0, okB0, w40, w41, off0, off1, hB0_0, hB0_1);
            gather_h(pAr1, pAc1, dsqA1, okA1, w40, w41, off0, off1, hA1_0, hA1_1);
            gather_h(pBr1, pBc1, dsqB1, okB1, w40, w41, off0, off1, hB1_0, hB1_1);

#pragma unroll
            for (int tt = 0; tt < 4; tt++) {
                int t = 4 * j + tt;
                unsigned ah00 = tf32_rnd(hA0_0[tt]), ah01 = tf32_rnd(hB0_0[tt]);
                unsigned ah02 = tf32_rnd(hA0_1[tt]), ah03 = tf32_rnd(hB0_1[tt]);
                unsigned ah10 = tf32_rnd(hA1_0[tt]), ah11 = tf32_rnd(hB1_0[tt]);
                unsigned ah12 = tf32_rnd(hA1_1[tt]), ah13 = tf32_rnd(hB1_1[tt]);

                const float2* wrow = sWf + (size_t)t * 8 * 32 + lane;
#pragma unroll
                for (int n = 0; n < 8; n++) {
                    float2 b = wrow[n * 32];
                    unsigned b0h = __float_as_uint(b.x);
                    unsigned b1h = __float_as_uint(b.y);
                    mma_tf32(acc0[n], ah00, ah01, ah02, ah03, b0h, b1h);
                    mma_tf32(acc1[n], ah10, ah11, ah12, ah13, b0h, b1h);
                }
            }
        }

        // ---- epilogue: pair-transpose, bias, RED.128 scatter ----
        int node0 = evenc ? colA0 : colB0;
        int node1 = evenc ? colA1 : colB1;
#pragma unroll
        for (int n = 0; n < 8; n++) {
            int colb = n * 8 + colBase0;
            float4 bb = *(const float4*)(bx2 + colb);
            {
                float o0 = __shfl_xor_sync(FULL, acc0[n][0], 1);
                float o1 = __shfl_xor_sync(FULL, acc0[n][1], 1);
                float o2 = __shfl_xor_sync(FULL, acc0[n][2], 1);
                float o3 = __shfl_xor_sync(FULL, acc0[n][3], 1);
                float4 q;
                if (evenc) q = make_float4(acc0[n][0], acc0[n][1], o0, o1);
                else       q = make_float4(o2, o3, acc0[n][2], acc0[n][3]);
                if (node0 >= 0) {
                    float* dst = outx + (size_t)node0 * F_DIM + colb;
                    asm volatile("red.global.add.v4.f32 [%0], {%1,%2,%3,%4};"
                                 :: "l"(dst),
                                    "f"(q.x + bb.x), "f"(q.y + bb.y),
                                    "f"(q.z + bb.z), "f"(q.w + bb.w)
                                 : "memory");
                }
            }
            {
                float o0 = __shfl_xor_sync(FULL, acc1[n][0], 1);
                float o1 = __shfl_xor_sync(FULL, acc1[n][1], 1);
                float o2 = __shfl_xor_sync(FULL, acc1[n][2], 1);
                float o3 = __shfl_xor_sync(FULL, acc1[n][3], 1);
                float4 q;
                if (evenc) q = make_float4(acc1[n][0], acc1[n][1], o0, o1);
                else       q = make_float4(o2, o3, acc1[n][2], acc1[n][3]);
                if (node1 >= 0) {
                    float* dst = outx + (size_t)node1 * F_DIM + colb;
                    asm volatile("red.global.add.v4.f32 [%0], {%1,%2,%3,%4};"
                                 :: "l"(dst),
                                    "f"(q.x + bb.x), "f"(q.y + bb.y),
                                    "f"(q.z + bb.z), "f"(q.w + bb.w)
                                 : "memory");
                }
            }
        }
    }
}

// ---------------------------------------------------------------------------
extern "C" void kernel_launch(void* const* d_in, const int* in_sizes, int n_in,
                              void* d_out, int out_size)
{
    const float* x   = (const float*)d_in[0];
    const float* pos = (const float*)d_in[1];
    const void*  ei  = d_in[2];
    const float* Wx1 = (const float*)d_in[3];
    const float* bx1 = (const float*)d_in[4];
    const float* Wx2 = (const float*)d_in[5];
    const float* bx2 = (const float*)d_in[6];
    const float* Wp1 = (const float*)d_in[7];
    const float* bp1 = (const float*)d_in[8];
    const float* Wp2 = (const float*)d_in[9];
    const float* bp2 = (const float*)d_in[10];

    int nNodes = in_sizes[0] / F_DIM;      // 100000
    int E      = in_sizes[2] / 2;          // 1000000

    float* outx   = (float*)d_out;                           // [N, 64]
    float* outpos = (float*)d_out + (size_t)nNodes * F_DIM;  // [N, 3]

    int nCheck = (E < 32) ? E : 32;
    size_t zeroCount = (size_t)nNodes * (F_DIM + 3);

    node_precompute<<<(nNodes + 7) / 8, 128>>>(
        x, Wx1, bx1, Wx2, Wp1, bp1, Wp2, bp2,
        (const long long*)ei, nCheck,
        (float*)d_out, zeroCount, nNodes);

    size_t shmem = sizeof(float2) * 16 * 8 * 32;   // 32 KB
    cudaFuncSetAttribute(edge_kernel, cudaFuncAttributeMaxDynamicSharedMemorySize, (int)shmem);
    edge_kernel<<<EDGE_BLOCKS, 128, shmem>>>(pos, ei, bx2, outx, outpos, E, nNodes);
}

// round 15
// speedup vs baseline: 1.0028x; 1.0028x over previous
#include <cuda_runtime.h>
#include <cstdint>

// ---------------------------------------------------------------------------
// EquivariantMessagePassing — GB300 sm_103a — Round 13
//
//   h_e = silu( A[row] + B[col] + dist_sq * Wx1[128,:] )   (A has bx1 baked in)
//   msg_x_e = h_e @ Wx2 + bx2    -> red.global.add.v4.f32 scatter to out_x[col]
//   pos_upd = wpos[row]*rel_pos  -> atomic scatter to out_pos[col]
// R13: PERSISTENT edge blocks (592 blocks loop over tiles; Wfrag staged once
// per block instead of 7813x) + tanh-based silu (1 MUFU instead of 2).
// Edge GEMM: single-term tf32 MMA, permuted A/B layout, 32 edges/warp.
// ---------------------------------------------------------------------------

#define MAX_N 100000
#define F_DIM 64
#define H_DIM 128
#define EDGE_BLOCKS 592

__device__ float  g_A[(size_t)MAX_N * H_DIM];     // permuted rows
__device__ float  g_B[(size_t)MAX_N * H_DIM];     // permuted rows
__device__ float  g_wpos[MAX_N];
__device__ int    g_idx_is64;
__device__ float2 g_Wfrag[16 * 8 * 32];           // [t][n][lane] = (b0hi, b1hi)
__device__ float  g_w128p[H_DIM];                 // permuted dist_sq weight row

__device__ __forceinline__ float silu_f(float v) {
    float t;
    asm("tanh.approx.f32 %0, %1;" : "=f"(t) : "f"(v * 0.5f));
    return v * fmaf(t, 0.5f, 0.5f);
}

__device__ __forceinline__ unsigned tf32_rnd(float v) {
    unsigned r;
    asm("cvt.rna.tf32.f32 %0, %1;" : "=r"(r) : "f"(v));
    return r;
}

__device__ __forceinline__ void mma_tf32(float acc[4],
                                         unsigned a0, unsigned a1, unsigned a2, unsigned a3,
                                         unsigned b0, unsigned b1) {
    asm volatile(
        "mma.sync.aligned.m16n8k8.row.col.f32.tf32.tf32.f32 "
        "{%0,%1,%2,%3}, {%4,%5,%6,%7}, {%8,%9}, {%0,%1,%2,%3};"
        : "+f"(acc[0]), "+f"(acc[1]), "+f"(acc[2]), "+f"(acc[3])
        : "r"(a0), "r"(a1), "r"(a2), "r"(a3), "r"(b0), "r"(b1));
}

__device__ __forceinline__ void load_edge(const void* ei, int e, int E, int is64,
                                          int nNodes, int& r, int& c)
{
    long long rv, cv;
    if (is64) {
        rv = ((const long long*)ei)[e];
        cv = ((const long long*)ei)[(size_t)E + e];
    } else {
        rv = ((const int*)ei)[e];
        cv = ((const int*)ei)[(size_t)E + e];
    }
    r = (rv >= 0 && rv < nNodes) ? (int)rv : -1;
    c = (cv >= 0 && cv < nNodes) ? (int)cv : -1;
    if (r < 0) c = -1;
}

// permutation: k = c*32 + h*16 + 4j + q  ->  p = j*32 + h*16 + c*4 + q
__device__ __host__ __forceinline__ int permute_k(int k) {
    int c = k >> 5;
    int rem = k & 31;
    int h = rem >> 4;
    int j = (rem >> 2) & 3;
    int q = k & 3;
    return j * 32 + h * 16 + c * 4 + q;
}

// gather + silu for one edge at permuted offsets off0 (h=0) / off1 (h=1)
__device__ __forceinline__ void gather_h(const float* pr, const float* pc,
                                         float dsq, bool ok,
                                         const float4& w40, const float4& w41,
                                         int off0, int off1,
                                         float h0[4], float h1[4])
{
    if (ok) {
        float4 a0 = *(const float4*)(pr + off0);
        float4 b0 = *(const float4*)(pc + off0);
        float4 a1 = *(const float4*)(pr + off1);
        float4 b1 = *(const float4*)(pc + off1);
        h0[0] = silu_f(a0.x + b0.x + dsq * w40.x);
        h0[1] = silu_f(a0.y + b0.y + dsq * w40.y);
        h0[2] = silu_f(a0.z + b0.z + dsq * w40.z);
        h0[3] = silu_f(a0.w + b0.w + dsq * w40.w);
        h1[0] = silu_f(a1.x + b1.x + dsq * w41.x);
        h1[1] = silu_f(a1.y + b1.y + dsq * w41.y);
        h1[2] = silu_f(a1.z + b1.z + dsq * w41.z);
        h1[3] = silu_f(a1.w + b1.w + dsq * w41.w);
    } else {
#pragma unroll
        for (int q = 0; q < 4; q++) { h0[q] = 0.f; h1[q] = 0.f; }
    }
}

// ---------------------------------------------------------------------------
// Kernel 1: per-node precompute (FFMA) + output zeroing + (block 0) prep
// ---------------------------------------------------------------------------
__global__ __launch_bounds__(128) void node_precompute(
    const float* __restrict__ x,
    const float* __restrict__ Wx1, const float* __restrict__ bx1,
    const float* __restrict__ Wx2,
    const float* __restrict__ Wp1, const float* __restrict__ bp1,
    const float* __restrict__ Wp2, const float* __restrict__ bp2,
    const long long* __restrict__ ei, int nCheck,
    float* __restrict__ out0, size_t zeroCount,
    int nNodes)
{
    const int NPB = 8;
    __shared__ float xs[NPB * F_DIM];
    __shared__ float wpart[4][NPB];

    int n0  = blockIdx.x * NPB;
    int tid = threadIdx.x;

    if (blockIdx.x == 0) {
        if (tid == 0) {
            int is64 = 1;
            for (int i = 0; i < nCheck; i++) {
                long long v = ei[i];
                if (v < 0 || v >= (long long)nNodes) { is64 = 0; break; }
            }
            g_idx_is64 = is64;
        }
        if (tid < H_DIM)
            g_w128p[permute_k(tid)] = Wx1[H_DIM * H_DIM + tid];
        for (int i = tid; i < 16 * 8 * 32; i += 128) {
            int lane = i & 31;
            int n    = (i >> 5) & 7;
            int t    = i >> 8;
            int c    = lane & 3;
            int gid  = lane >> 2;
            int col  = n * 8 + gid;
            int k0   = c * 32 + t;
            int k1   = k0 + 16;
            unsigned h0 = tf32_rnd(Wx2[k0 * F_DIM + col]);
            unsigned h1 = tf32_rnd(Wx2[k1 * F_DIM + col]);
            g_Wfrag[i] = make_float2(__uint_as_float(h0), __uint_as_float(h1));
        }
    }

    for (size_t i = (size_t)blockIdx.x * blockDim.x + tid; i < zeroCount;
         i += (size_t)gridDim.x * blockDim.x)
        out0[i] = 0.0f;

    for (int i = tid; i < NPB * F_DIM; i += 128) {
        int node = n0 + (i >> 6);
        xs[i] = (node < nNodes) ? x[(size_t)n0 * F_DIM + i] : 0.0f;
    }
    __syncthreads();

    float accA[NPB], accB[NPB], accP[NPB];
#pragma unroll
    for (int m = 0; m < NPB; m++) { accA[m] = 0.f; accB[m] = 0.f; accP[m] = 0.f; }

    const float* wx1a = Wx1 + tid;
    const float* wx1b = Wx1 + 64 * H_DIM + tid;
    const float* wp1c = Wp1 + tid;

#pragma unroll 4
    for (int k = 0; k < F_DIM; k++) {
        float w1 = wx1a[k * H_DIM];
        float w2 = wx1b[k * H_DIM];
        float wp = wp1c[k * H_DIM];
#pragma unroll
        for (int m = 0; m < NPB; m++) {
            float xv = xs[m * F_DIM + k];
            accA[m] = fmaf(xv, w1, accA[m]);
            accB[m] = fmaf(xv, w2, accB[m]);
            accP[m] = fmaf(xv, wp, accP[m]);
        }
    }

    float b1  = bx1[tid];
    float bp  = bp1[tid];
    float w2v = Wp2[tid];
    int   pt  = permute_k(tid);   // permuted column for A/B stores

#pragma unroll
    for (int m = 0; m < NPB; m++) {
        int node = n0 + m;
        if (node < nNodes) {
            g_A[(size_t)node * H_DIM + pt] = accA[m] + b1;
            g_B[(size_t)node * H_DIM + pt] = accB[m];
        }
        float hv = accP[m] + bp;
        float contrib = silu_f(hv) * w2v;
#pragma unroll
        for (int off = 16; off; off >>= 1)
            contrib += __shfl_xor_sync(0xffffffffu, contrib, off);
        if ((tid & 31) == 0) wpart[tid >> 5][m] = contrib;
    }
    __syncthreads();

    if (tid < NPB) {
        int node = n0 + tid;
        if (node < nNodes)
            g_wpos[node] = wpart[0][tid] + wpart[1][tid] + wpart[2][tid] + wpart[3][tid] + bp2[0];
    }
}

// ---------------------------------------------------------------------------
// Kernel 2: PERSISTENT edge kernel. 592 blocks x 128 threads, 4 blocks/SM.
// Each block stages Wfrag once, then loops over 128-edge tiles.
// 32 edges/warp (two m16 tiles), single-term tf32 MMA.
// ---------------------------------------------------------------------------
__global__ __launch_bounds__(128, 4) void edge_kernel(
    const float* __restrict__ pos,
    const void*  __restrict__ ei,
    const float* __restrict__ bx2,
    float* __restrict__ outx,           // [N, 64]
    float* __restrict__ outpos,         // [N, 3]
    int E, int nNodes)
{
    extern __shared__ float2 sWf[];     // 16*8*32 float2 = 32KB

    const unsigned FULL = 0xffffffffu;
    int tid   = threadIdx.x;
    int lane  = tid & 31;
    int warp  = tid >> 5;
    int is64  = g_idx_is64;

    // ---- one-time Wfrag stage ----
#pragma unroll
    for (int i = 0; i < 32; i++)
        sWf[i * 128 + tid] = g_Wfrag[i * 128 + tid];
    __syncthreads();   // sWf read-only hereafter; no barriers inside the loop

    int gid = lane >> 2;
    int c   = lane & 3;
    bool evenc = ((c & 1) == 0);
    int  colBase0 = evenc ? (2 * c) : (2 * c - 2);

    for (int base = blockIdx.x * 128; base < E; base += EDGE_BLOCKS * 128) {
        int warpE = base + warp * 32;

        // ---- per-lane edge (one edge per lane, 32 edges/warp) ----
        int   rIdx = -1, cIdx = -1;
        float dsq  = 0.f;
        {
            int gE = warpE + lane;
            if (gE < E) load_edge(ei, gE, E, is64, nNodes, rIdx, cIdx);
            if (cIdx >= 0) {
                float dx = pos[rIdx * 3 + 0] - pos[cIdx * 3 + 0];
                float dy = pos[rIdx * 3 + 1] - pos[cIdx * 3 + 1];
                float dz = pos[rIdx * 3 + 2] - pos[cIdx * 3 + 2];
                dsq = dx * dx + dy * dy + dz * dz;
                float wp = g_wpos[rIdx];
                atomicAdd(&outpos[(size_t)cIdx * 3 + 0], wp * dx);
                atomicAdd(&outpos[(size_t)cIdx * 3 + 1], wp * dy);
                atomicAdd(&outpos[(size_t)cIdx * 3 + 2], wp * dz);
            }
        }

        int   rowA0 = __shfl_sync(FULL, rIdx, gid);
        int   colA0 = __shfl_sync(FULL, cIdx, gid);
        float dsqA0 = __shfl_sync(FULL, dsq,  gid);
        int   rowB0 = __shfl_sync(FULL, rIdx, gid + 8);
        int   colB0 = __shfl_sync(FULL, cIdx, gid + 8);
        float dsqB0 = __shfl_sync(FULL, dsq,  gid + 8);
        int   rowA1 = __shfl_sync(FULL, rIdx, gid + 16);
        int   colA1 = __shfl_sync(FULL, cIdx, gid + 16);
        float dsqA1 = __shfl_sync(FULL, dsq,  gid + 16);
        int   rowB1 = __shfl_sync(FULL, rIdx, gid + 24);
        int   colB1 = __shfl_sync(FULL, cIdx, gid + 24);
        float dsqB1 = __shfl_sync(FULL, dsq,  gid + 24);

        bool okA0 = (colA0 >= 0), okB0 = (colB0 >= 0);
        bool okA1 = (colA1 >= 0), okB1 = (colB1 >= 0);
        const float* pAr0 = okA0 ? g_A + (size_t)rowA0 * H_DIM : g_A;
        const float* pAc0 = okA0 ? g_B + (size_t)colA0 * H_DIM : g_B;
        const float* pBr0 = okB0 ? g_A + (size_t)rowB0 * H_DIM : g_A;
        const float* pBc0 = okB0 ? g_B + (size_t)colB0 * H_DIM : g_B;
        const float* pAr1 = okA1 ? g_A + (size_t)rowA1 * H_DIM : g_A;
        const float* pAc1 = okA1 ? g_B + (size_t)colA1 * H_DIM : g_B;
        const float* pBr1 = okB1 ? g_A + (size_t)rowB1 * H_DIM : g_A;
        const float* pBc1 = okB1 ? g_B + (size_t)colB1 * H_DIM : g_B;

        float acc0[8][4], acc1[8][4];
#pragma unroll
        for (int n = 0; n < 8; n++)
#pragma unroll
            for (int q = 0; q < 4; q++) { acc0[n][q] = 0.f; acc1[n][q] = 0.f; }

#pragma unroll
        for (int j = 0; j < 4; j++) {
            int off0 = j * 32 + c * 4;
            int off1 = off0 + 16;
            float4 w40 = *(const float4*)(g_w128p + off0);
            float4 w41 = *(const float4*)(g_w128p + off1);

            float hA0_0[4], hA0_1[4], hB0_0[4], hB0_1[4];
            float hA1_0[4], hA1_1[4], hB1_0[4], hB1_1[4];
            gather_h(pAr0, pAc0, dsqA0, okA0, w40, w41, off0, off1, hA0_0, hA0_1);
            gather_h(pBr0, pBc0, dsqB0, okB0, w40, w41, off0, off1, hB0_0, hB0_1);
            gather_h(pAr1, pAc1, dsqA1, okA1, w40, w41, off0, off1, hA1_0, hA1_1);
            gather_h(pBr1, pBc1, dsqB1, okB1, w40, w41, off0, off1, hB1_0, hB1_1);

#pragma unroll
            for (int tt = 0; tt < 4; tt++) {
                int t = 4 * j + tt;
                unsigned ah00 = tf32_rnd(hA0_0[tt]), ah01 = tf32_rnd(hB0_0[tt]);
                unsigned ah02 = tf32_rnd(hA0_1[tt]), ah03 = tf32_rnd(hB0_1[tt]);
                unsigned ah10 = tf32_rnd(hA1_0[tt]), ah11 = tf32_rnd(hB1_0[tt]);
                unsigned ah12 = tf32_rnd(hA1_1[tt]), ah13 = tf32_rnd(hB1_1[tt]);

                const float2* wrow = sWf + (size_t)t * 8 * 32 + lane;
#pragma unroll
                for (int n = 0; n < 8; n++) {
                    float2 b = wrow[n * 32];
                    unsigned b0h = __float_as_uint(b.x);
                    unsigned b1h = __float_as_uint(b.y);
                    mma_tf32(acc0[n], ah00, ah01, ah02, ah03, b0h, b1h);
                    mma_tf32(acc1[n], ah10, ah11, ah12, ah13, b0h, b1h);
                }
            }
        }

        // ---- epilogue: pair-transpose, bias, RED.128 scatter ----
        int node0 = evenc ? colA0 : colB0;
        int node1 = evenc ? colA1 : colB1;
#pragma unroll
        for (int n = 0; n < 8; n++) {
            int colb = n * 8 + colBase0;
            float4 bb = *(const float4*)(bx2 + colb);
            {
                float o0 = __shfl_xor_sync(FULL, acc0[n][0], 1);
                float o1 = __shfl_xor_sync(FULL, acc0[n][1], 1);
                float o2 = __shfl_xor_sync(FULL, acc0[n][2], 1);
                float o3 = __shfl_xor_sync(FULL, acc0[n][3], 1);
                float4 q;
                if (evenc) q = make_float4(acc0[n][0], acc0[n][1], o0, o1);
                else       q = make_float4(o2, o3, acc0[n][2], acc0[n][3]);
                if (node0 >= 0) {
                    float* dst = outx + (size_t)node0 * F_DIM + colb;
                    asm volatile("red.global.add.v4.f32 [%0], {%1,%2,%3,%4};"
                                 :: "l"(dst),
                                    "f"(q.x + bb.x), "f"(q.y + bb.y),
                                    "f"(q.z + bb.z), "f"(q.w + bb.w)
                                 : "memory");
                }
            }
            {
                float o0 = __shfl_xor_sync(FULL, acc1[n][0], 1);
                float o1 = __shfl_xor_sync(FULL, acc1[n][1], 1);
                float o2 = __shfl_xor_sync(FULL, acc1[n][2], 1);
                float o3 = __shfl_xor_sync(FULL, acc1[n][3], 1);
                float4 q;
                if (evenc) q = make_float4(acc1[n][0], acc1[n][1], o0, o1);
                else       q = make_float4(o2, o3, acc1[n][2], acc1[n][3]);
                if (node1 >= 0) {
                    float* dst = outx + (size_t)node1 * F_DIM + colb;
                    asm volatile("red.global.add.v4.f32 [%0], {%1,%2,%3,%4};"
                                 :: "l"(dst),
                                    "f"(q.x + bb.x), "f"(q.y + bb.y),
                                    "f"(q.z + bb.z), "f"(q.w + bb.w)
                                 : "memory");
                }
            }
        }
    }
}

// ---------------------------------------------------------------------------
extern "C" void kernel_launch(void* const* d_in, const int* in_sizes, int n_in,
                              void* d_out, int out_size)
{
    const float* x   = (const float*)d_in[0];
    const float* pos = (const float*)d_in[1];
    const void*  ei  = d_in[2];
    const float* Wx1 = (const float*)d_in[3];
    const float* bx1 = (const float*)d_in[4];
    const float* Wx2 = (const float*)d_in[5];
    const float* bx2 = (const float*)d_in[6];
    const float* Wp1 = (const float*)d_in[7];
    const float* bp1 = (const float*)d_in[8];
    const float* Wp2 = (const float*)d_in[9];
    const float* bp2 = (const float*)d_in[10];

    int nNodes = in_sizes[0] / F_DIM;      // 100000
    int E      = in_sizes[2] / 2;          // 1000000

    float* outx   = (float*)d_out;                           // [N, 64]
    float* outpos = (float*)d_out + (size_t)nNodes * F_DIM;  // [N, 3]

    int nCheck = (E < 32) ? E : 32;
    size_t zeroCount = (size_t)nNodes * (F_DIM + 3);

    node_precompute<<<(nNodes + 7) / 8, 128>>>(
        x, Wx1, bx1, Wx2, Wp1, bp1, Wp2, bp2,
        (const long long*)ei, nCheck,
        (float*)d_out, zeroCount, nNodes);

    size_t shmem = sizeof(float2) * 16 * 8 * 32;   // 32 KB
    cudaFuncSetAttribute(edge_kernel, cudaFuncAttributeMaxDynamicSharedMemorySize, (int)shmem);
    edge_kernel<<<EDGE_BLOCKS, 128, shmem>>>(pos, ei, bx2, outx, outpos, E, nNodes);
}